// round 2
// baseline (speedup 1.0000x reference)
#include <cuda_runtime.h>

#define H 128
#define NMAX 100000

// Scratch: per-node precomputed A = z@W1_top + b1 (cols 0..127),
//          B = z@W1_bot (cols 128..255). 100000*256*4 = 102.4 MB.
__device__ float g_AB[(size_t)NMAX * 256];
__device__ int g_idx_is64;

// ---------------- dtype detection for edge_label_index ----------------
// If the buffer really holds int64 node indices, every 64-bit word is in
// [0, NMAX). If it holds int32 indices, a 64-bit read packs two indices
// (lo + hi*2^32) and is >= 2^32 whenever hi != 0 (hi==0 has prob 1e-5).
__global__ void detect_idx_kernel(const long long* __restrict__ p, int n64)
{
    int bad = 0;
    for (int i = threadIdx.x; i < n64; i += blockDim.x) {
        long long v = p[i];
        if (v < 0 || v >= NMAX) bad = 1;
    }
    bad = __syncthreads_or(bad);
    if (threadIdx.x == 0) g_idx_is64 = bad ? 0 : 1;
}

// ---------------- GEMM: g_AB[m, n] = sum_k z[m,k] * Wcat[k,n] (+ b1 for n<128)
// Wcat[k,n] = (n < 128) ? W1[k, n] : W1[k+128, n-128]
#define BM 128
#define BN 64
#define BK 32

__global__ __launch_bounds__(256) void node_gemm_kernel(
    const float* __restrict__ z,
    const float* __restrict__ W1,
    const float* __restrict__ b1,
    int n_nodes)
{
    __shared__ float As[BK][BM];   // transposed z tile: 16 KB
    __shared__ float Ws[BK][BN];   // 8 KB

    const int m0 = blockIdx.x * BM;
    const int n0 = blockIdx.y * BN;         // 0,64,128,192 (each tile fully in one half)
    const int tid = threadIdx.x;            // 256 threads
    const int tx = tid & 15;                // col group: cols tx*4 .. tx*4+3
    const int ty = tid >> 4;                // row group: rows ty*8 .. ty*8+7

    float acc[8][4];
    #pragma unroll
    for (int i = 0; i < 8; i++)
        #pragma unroll
        for (int j = 0; j < 4; j++) acc[i][j] = 0.f;

    for (int kk = 0; kk < H; kk += BK) {
        // Load z tile [BM x BK] -> As transposed. 1024 float4, 4 per thread.
        #pragma unroll
        for (int i = 0; i < 4; i++) {
            int lin = tid + i * 256;        // 0..1023
            int m   = lin >> 3;             // 0..127
            int kq  = lin & 7;              // float4 slot in k
            float4 v = make_float4(0.f, 0.f, 0.f, 0.f);
            if (m0 + m < n_nodes)
                v = *(const float4*)(z + (size_t)(m0 + m) * H + kk + kq * 4);
            As[kq * 4 + 0][m] = v.x;
            As[kq * 4 + 1][m] = v.y;
            As[kq * 4 + 2][m] = v.z;
            As[kq * 4 + 3][m] = v.w;
        }
        // Load W tile [BK x BN]. 512 float4, 2 per thread.
        #pragma unroll
        for (int i = 0; i < 2; i++) {
            int lin = tid + i * 256;        // 0..511
            int k   = lin >> 4;             // 0..31
            int n4  = lin & 15;             // float4 slot in n
            int kg  = kk + k;
            const float* wrow = (n0 < H) ? (W1 + (size_t)kg * H + n0)
                                         : (W1 + (size_t)(kg + H) * H + (n0 - H));
            *(float4*)(&Ws[k][n4 * 4]) = *(const float4*)(wrow + n4 * 4);
        }
        __syncthreads();

        #pragma unroll
        for (int k = 0; k < BK; k++) {
            float a[8], b[4];
            #pragma unroll
            for (int i = 0; i < 8; i++) a[i] = As[k][ty * 8 + i];
            #pragma unroll
            for (int j = 0; j < 4; j++) b[j] = Ws[k][tx * 4 + j];
            #pragma unroll
            for (int i = 0; i < 8; i++)
                #pragma unroll
                for (int j = 0; j < 4; j++)
                    acc[i][j] = fmaf(a[i], b[j], acc[i][j]);
        }
        __syncthreads();
    }

    // Epilogue: bake b1 into the A half (n < 128) so the edge pass skips it.
    const bool top_half = (n0 < H);
    #pragma unroll
    for (int i = 0; i < 8; i++) {
        int m = m0 + ty * 8 + i;
        if (m >= n_nodes) continue;
        #pragma unroll
        for (int j = 0; j < 4; j++) {
            int n = n0 + tx * 4 + j;
            float v = acc[i][j];
            if (top_half) v += b1[n];
            g_AB[(size_t)m * 256 + n] = v;
        }
    }
}

// ---------------- Edge pass: one warp per edge.
// out[e] = sum_j relu(A[row][j] + B[col][j]) * W2[j] + b2
__global__ __launch_bounds__(256) void edge_kernel(
    const void* __restrict__ eli_raw,    // [2, E] int32 or int64
    const float* __restrict__ W2,        // [128]
    const float* __restrict__ b2,        // [1]
    float* __restrict__ out,
    int E, int n_nodes)
{
    __shared__ float4 w2s[32];
    const int tid = threadIdx.x;
    if (tid < 32) w2s[tid] = ((const float4*)W2)[tid];
    __syncthreads();

    const int lane = tid & 31;
    const int e = blockIdx.x * 8 + (tid >> 5);   // 8 warps per 256-thread CTA
    if (e >= E) return;

    long long r, c;
    if (g_idx_is64) {
        const long long* p = (const long long*)eli_raw;
        r = p[e];
        c = p[(size_t)E + e];
    } else {
        const int* p = (const int*)eli_raw;
        r = p[e];
        c = p[(size_t)E + e];
    }
    // Defensive clamp: a wrong interpretation yields rel_err, not a crash.
    r = min(max(r, 0LL), (long long)(n_nodes - 1));
    c = min(max(c, 0LL), (long long)(n_nodes - 1));

    float4 a = *(const float4*)(g_AB + (size_t)r * 256 + lane * 4);
    float4 b = *(const float4*)(g_AB + (size_t)c * 256 + 128 + lane * 4);
    float4 w = w2s[lane];

    float s = fmaxf(a.x + b.x, 0.f) * w.x
            + fmaxf(a.y + b.y, 0.f) * w.y
            + fmaxf(a.z + b.z, 0.f) * w.z
            + fmaxf(a.w + b.w, 0.f) * w.w;

    #pragma unroll
    for (int o = 16; o; o >>= 1) s += __shfl_xor_sync(0xffffffffu, s, o);

    if (lane == 0) out[e] = s + b2[0];
}

extern "C" void kernel_launch(void* const* d_in, const int* in_sizes, int n_in,
                              void* d_out, int out_size)
{
    const float* z   = (const float*)d_in[0];
    const void*  eli = d_in[1];
    const float* W1  = (const float*)d_in[2];
    const float* b1  = (const float*)d_in[3];
    const float* W2  = (const float*)d_in[4];
    const float* b2  = (const float*)d_in[5];
    float*       out = (float*)d_out;

    const int n_nodes = in_sizes[0] / H;
    const int E = out_size;

    // Detect index dtype. Scanning min(4096, E) 64-bit words is safe under
    // both interpretations (int32 buffer holds E such words; int64 holds 2E).
    int n64 = E < 4096 ? E : 4096;
    detect_idx_kernel<<<1, 256>>>((const long long*)eli, n64);

    dim3 g1((n_nodes + BM - 1) / BM, 256 / BN);
    node_gemm_kernel<<<g1, 256>>>(z, W1, b1, n_nodes);

    int blocks = (E + 7) / 8;
    edge_kernel<<<blocks, 256>>>(eli, W2, b2, out, E, n_nodes);
}

// round 4
// speedup vs baseline: 1.3921x; 1.3921x over previous
#include <cuda_runtime.h>
#include <cuda_bf16.h>
#include <cstdint>

#define H 128
#define NMAX 100000

// Scratch: per-node A = z@W1_top + b1 (cols 0..127), B = z@W1_bot (cols 128..255)
__device__ float g_AB[(size_t)NMAX * 256];
__device__ int g_idx_is64;
// Pre-transposed Wcat^T as bf16 hi/lo: layout [n][k], n in [0,256), k in [0,128)
__device__ __align__(16) __nv_bfloat16 g_Wt_hi[256 * 128];
__device__ __align__(16) __nv_bfloat16 g_Wt_lo[256 * 128];

// ---------------- index dtype detection ----------------
__global__ void detect_idx_kernel(const long long* __restrict__ p, int n64) {
    int bad = 0;
    for (int i = threadIdx.x; i < n64; i += blockDim.x) {
        long long v = p[i];
        if (v < 0 || v >= NMAX) bad = 1;
    }
    bad = __syncthreads_or(bad);
    if (threadIdx.x == 0) g_idx_is64 = bad ? 0 : 1;
}

// ---------------- W^T prep: Wt[n][k] = Wcat[k][n], split to bf16 hi/lo ----------------
__global__ void prep_w_kernel(const float* __restrict__ W1) {
    int idx = blockIdx.x * blockDim.x + threadIdx.x;   // 32768
    if (idx >= 256 * 128) return;
    int n = idx & 255;            // consecutive tid -> consecutive n (coalesced W1 read)
    int k = idx >> 8;
    float v = (n < 128) ? W1[(size_t)k * 128 + n] : W1[(size_t)(k + 128) * 128 + (n - 128)];
    __nv_bfloat16 hi = __float2bfloat16(v);
    __nv_bfloat16 lo = __float2bfloat16(v - __bfloat162float(hi));
    g_Wt_hi[(size_t)n * 128 + k] = hi;
    g_Wt_lo[(size_t)n * 128 + k] = lo;
}

// ---------------- bf16-split tensor-core GEMM via mma.sync ----------------
// g_AB[m, half*128 + n] = sum_k z[m,k]*Wcat[k, half*128+n]  (+ b1 when half==0)
#define ASTRIDE 136   // bf16 elems per SMEM row (padding -> conflict-free frags)

__device__ __forceinline__ void mma16816(float* d, const uint32_t* a, const uint32_t* b) {
    asm volatile(
        "mma.sync.aligned.m16n8k16.row.col.f32.bf16.bf16.f32 "
        "{%0,%1,%2,%3}, {%4,%5,%6,%7}, {%8,%9}, {%0,%1,%2,%3};"
        : "+f"(d[0]), "+f"(d[1]), "+f"(d[2]), "+f"(d[3])
        : "r"(a[0]), "r"(a[1]), "r"(a[2]), "r"(a[3]), "r"(b[0]), "r"(b[1]));
}

__global__ __launch_bounds__(256, 1) void node_gemm_mma(
    const float* __restrict__ z,
    const float* __restrict__ b1,
    int n_nodes)
{
    extern __shared__ __align__(16) unsigned char smem[];
    __nv_bfloat16* Ah = (__nv_bfloat16*)smem;            // [128][ASTRIDE]
    __nv_bfloat16* Al = Ah + 128 * ASTRIDE;
    __nv_bfloat16* Bh = Al + 128 * ASTRIDE;              // [128 n][ASTRIDE k]
    __nv_bfloat16* Bl = Bh + 128 * ASTRIDE;

    const int tid = threadIdx.x;
    const int wid = tid >> 5;
    const int lane = tid & 31;
    const int m0 = blockIdx.x * 128;
    const int half = blockIdx.y;                          // 0 or 1 (N half)

    // ---- load z tile [128 x 128] fp32 -> bf16 hi/lo ----
    #pragma unroll
    for (int i = 0; i < 16; i++) {
        int idx = tid + i * 256;        // 0..4095 float4 slots
        int r = idx >> 5;               // row 0..127
        int c4 = idx & 31;              // float4 slot
        float4 v = make_float4(0.f, 0.f, 0.f, 0.f);
        if (m0 + r < n_nodes)
            v = *(const float4*)(z + (size_t)(m0 + r) * H + c4 * 4);
        __nv_bfloat16 h0 = __float2bfloat16(v.x), h1 = __float2bfloat16(v.y);
        __nv_bfloat16 h2 = __float2bfloat16(v.z), h3 = __float2bfloat16(v.w);
        __nv_bfloat16 l0 = __float2bfloat16(v.x - __bfloat162float(h0));
        __nv_bfloat16 l1 = __float2bfloat16(v.y - __bfloat162float(h1));
        __nv_bfloat16 l2 = __float2bfloat16(v.z - __bfloat162float(h2));
        __nv_bfloat16 l3 = __float2bfloat16(v.w - __bfloat162float(h3));
        uint2 uh, ul;
        uh.x = ((uint32_t)__bfloat16_as_ushort(h1) << 16) | __bfloat16_as_ushort(h0);
        uh.y = ((uint32_t)__bfloat16_as_ushort(h3) << 16) | __bfloat16_as_ushort(h2);
        ul.x = ((uint32_t)__bfloat16_as_ushort(l1) << 16) | __bfloat16_as_ushort(l0);
        ul.y = ((uint32_t)__bfloat16_as_ushort(l3) << 16) | __bfloat16_as_ushort(l2);
        *(uint2*)((unsigned char*)Ah + r * (ASTRIDE * 2) + c4 * 8) = uh;
        *(uint2*)((unsigned char*)Al + r * (ASTRIDE * 2) + c4 * 8) = ul;
    }

    // ---- copy pre-transposed W images (coalesced uint4) ----
    {
        const uint4* shi = (const uint4*)(g_Wt_hi + (size_t)half * 128 * 128);
        const uint4* slo = (const uint4*)(g_Wt_lo + (size_t)half * 128 * 128);
        #pragma unroll
        for (int i = 0; i < 8; i++) {
            int idx = tid + i * 256;    // 0..2047 (128 rows x 16 uint4)
            int r = idx >> 4;
            int q = idx & 15;
            *(uint4*)((unsigned char*)Bh + r * (ASTRIDE * 2) + q * 16) = shi[r * 16 + q];
            *(uint4*)((unsigned char*)Bl + r * (ASTRIDE * 2) + q * 16) = slo[r * 16 + q];
        }
    }
    __syncthreads();

    // ---- compute: warp tile 32(M) x 64(N), 3-pass bf16 split ----
    const int wm = wid & 3;             // 4 warps along M
    const int wn = wid >> 2;            // 2 warps along N
    const int gr = lane >> 2;
    const int cc = lane & 3;

    float acc[2][8][4];
    #pragma unroll
    for (int a = 0; a < 2; a++)
        #pragma unroll
        for (int b = 0; b < 8; b++)
            #pragma unroll
            for (int c = 0; c < 4; c++) acc[a][b][c] = 0.f;

    #pragma unroll
    for (int ks = 0; ks < 8; ks++) {
        const int kb = ks * 32 + cc * 4;          // byte offset of k fragment pair
        uint32_t ah[2][4], al[2][4];
        #pragma unroll
        for (int mt = 0; mt < 2; mt++) {
            int row = wm * 32 + mt * 16 + gr;
            const unsigned char* pAh = (const unsigned char*)Ah + kb;
            const unsigned char* pAl = (const unsigned char*)Al + kb;
            ah[mt][0] = *(const uint32_t*)(pAh + (row)     * (ASTRIDE * 2));
            ah[mt][1] = *(const uint32_t*)(pAh + (row + 8) * (ASTRIDE * 2));
            ah[mt][2] = *(const uint32_t*)(pAh + (row)     * (ASTRIDE * 2) + 16);
            ah[mt][3] = *(const uint32_t*)(pAh + (row + 8) * (ASTRIDE * 2) + 16);
            al[mt][0] = *(const uint32_t*)(pAl + (row)     * (ASTRIDE * 2));
            al[mt][1] = *(const uint32_t*)(pAl + (row + 8) * (ASTRIDE * 2));
            al[mt][2] = *(const uint32_t*)(pAl + (row)     * (ASTRIDE * 2) + 16);
            al[mt][3] = *(const uint32_t*)(pAl + (row + 8) * (ASTRIDE * 2) + 16);
        }
        #pragma unroll
        for (int nt = 0; nt < 8; nt++) {
            int nrow = wn * 64 + nt * 8 + gr;     // B col (n) = groupID
            const unsigned char* pB = (const unsigned char*)Bh + nrow * (ASTRIDE * 2) + kb;
            const unsigned char* pBl = (const unsigned char*)Bl + nrow * (ASTRIDE * 2) + kb;
            uint32_t bh[2], bl[2];
            bh[0] = *(const uint32_t*)(pB);
            bh[1] = *(const uint32_t*)(pB + 16);
            bl[0] = *(const uint32_t*)(pBl);
            bl[1] = *(const uint32_t*)(pBl + 16);
            #pragma unroll
            for (int mt = 0; mt < 2; mt++) {
                mma16816(acc[mt][nt], ah[mt], bh);
                mma16816(acc[mt][nt], al[mt], bh);
                mma16816(acc[mt][nt], ah[mt], bl);
            }
        }
    }

    // ---- epilogue: write fp32 pairs to g_AB, fuse b1 on half 0 ----
    #pragma unroll
    for (int mt = 0; mt < 2; mt++) {
        #pragma unroll
        for (int nt = 0; nt < 8; nt++) {
            int nloc = wn * 64 + nt * 8 + cc * 2;         // local col (pair start)
            int ncol = half * 128 + nloc;
            float bx = 0.f, by = 0.f;
            if (half == 0) {
                float2 bb = __ldg((const float2*)(b1 + nloc));
                bx = bb.x; by = bb.y;
            }
            int row0 = m0 + wm * 32 + mt * 16 + gr;
            if (row0 < n_nodes) {
                float2 v = make_float2(acc[mt][nt][0] + bx, acc[mt][nt][1] + by);
                *(float2*)(g_AB + (size_t)row0 * 256 + ncol) = v;
            }
            int row1 = row0 + 8;
            if (row1 < n_nodes) {
                float2 v = make_float2(acc[mt][nt][2] + bx, acc[mt][nt][3] + by);
                *(float2*)(g_AB + (size_t)row1 * 256 + ncol) = v;
            }
        }
    }
}

#define SMEM_GEMM (4 * 128 * ASTRIDE * 2)   // 139264 bytes

// ---------------- Edge pass: one warp per edge ----------------
__global__ __launch_bounds__(256) void edge_kernel(
    const void* __restrict__ eli_raw,
    const float* __restrict__ W2,
    const float* __restrict__ b2,
    float* __restrict__ out,
    int E, int n_nodes)
{
    __shared__ float4 w2s[32];
    const int tid = threadIdx.x;
    if (tid < 32) w2s[tid] = ((const float4*)W2)[tid];
    __syncthreads();

    const int lane = tid & 31;
    const int e = blockIdx.x * 8 + (tid >> 5);
    if (e >= E) return;

    long long r, c;
    if (g_idx_is64) {
        const long long* p = (const long long*)eli_raw;
        r = p[e];
        c = p[(size_t)E + e];
    } else {
        const int* p = (const int*)eli_raw;
        r = p[e];
        c = p[(size_t)E + e];
    }
    r = min(max(r, 0LL), (long long)(n_nodes - 1));
    c = min(max(c, 0LL), (long long)(n_nodes - 1));

    float4 a = *(const float4*)(g_AB + (size_t)r * 256 + lane * 4);
    float4 b = *(const float4*)(g_AB + (size_t)c * 256 + 128 + lane * 4);
    float4 w = w2s[lane];

    float s = fmaxf(a.x + b.x, 0.f) * w.x
            + fmaxf(a.y + b.y, 0.f) * w.y
            + fmaxf(a.z + b.z, 0.f) * w.z
            + fmaxf(a.w + b.w, 0.f) * w.w;

    #pragma unroll
    for (int o = 16; o; o >>= 1) s += __shfl_xor_sync(0xffffffffu, s, o);

    if (lane == 0) out[e] = s + b2[0];
}

extern "C" void kernel_launch(void* const* d_in, const int* in_sizes, int n_in,
                              void* d_out, int out_size)
{
    const float* z   = (const float*)d_in[0];
    const void*  eli = d_in[1];
    const float* W1  = (const float*)d_in[2];
    const float* b1  = (const float*)d_in[3];
    const float* W2  = (const float*)d_in[4];
    const float* b2  = (const float*)d_in[5];
    float*       out = (float*)d_out;

    const int n_nodes = in_sizes[0] / H;
    const int E = out_size;

    int n64 = E < 2048 ? E : 2048;
    detect_idx_kernel<<<1, 1024>>>((const long long*)eli, n64);

    prep_w_kernel<<<32, 1024>>>(W1);

    cudaFuncSetAttribute(node_gemm_mma, cudaFuncAttributeMaxDynamicSharedMemorySize,
                         SMEM_GEMM);
    dim3 g1((n_nodes + 127) / 128, 2);
    node_gemm_mma<<<g1, 256, SMEM_GEMM>>>(z, b1, n_nodes);

    int blocks = (E + 7) / 8;
    edge_kernel<<<blocks, 256>>>(eli, W2, b2, out, E, n_nodes);
}

// round 5
// speedup vs baseline: 2.3108x; 1.6600x over previous
#include <cuda_runtime.h>
#include <cuda_bf16.h>
#include <cuda_fp16.h>
#include <cstdint>

#define H 128
#define NMAX 100000

// Scratch: per-node A = z@W1_top + b1 (cols 0..127), B = z@W1_bot (cols 128..255), fp16
__device__ __align__(16) __half g_ABh[(size_t)NMAX * 256];
__device__ int g_idx_is64;
// Pre-transposed Wcat^T as bf16 hi/lo: layout [n][k], n in [0,256), k in [0,128)
__device__ __align__(16) __nv_bfloat16 g_Wt_hi[256 * 128];
__device__ __align__(16) __nv_bfloat16 g_Wt_lo[256 * 128];

// ---------------- index dtype detection ----------------
__global__ void detect_idx_kernel(const long long* __restrict__ p, int n64) {
    int bad = 0;
    for (int i = threadIdx.x; i < n64; i += blockDim.x) {
        long long v = p[i];
        if (v < 0 || v >= NMAX) bad = 1;
    }
    bad = __syncthreads_or(bad);
    if (threadIdx.x == 0) g_idx_is64 = bad ? 0 : 1;
}

// ---------------- W^T prep: Wt[n][k] = Wcat[k][n], split to bf16 hi/lo ----------------
__global__ void prep_w_kernel(const float* __restrict__ W1) {
    int idx = blockIdx.x * blockDim.x + threadIdx.x;   // 32768
    if (idx >= 256 * 128) return;
    int n = idx & 255;
    int k = idx >> 8;
    float v = (n < 128) ? W1[(size_t)k * 128 + n] : W1[(size_t)(k + 128) * 128 + (n - 128)];
    __nv_bfloat16 hi = __float2bfloat16(v);
    __nv_bfloat16 lo = __float2bfloat16(v - __bfloat162float(hi));
    g_Wt_hi[(size_t)n * 128 + k] = hi;
    g_Wt_lo[(size_t)n * 128 + k] = lo;
}

// ---------------- bf16-split tensor-core GEMM via mma.sync ----------------
#define ASTRIDE 136   // bf16 elems per SMEM row (padding -> conflict-free frags)

__device__ __forceinline__ void mma16816(float* d, const uint32_t* a, const uint32_t* b) {
    asm volatile(
        "mma.sync.aligned.m16n8k16.row.col.f32.bf16.bf16.f32 "
        "{%0,%1,%2,%3}, {%4,%5,%6,%7}, {%8,%9}, {%0,%1,%2,%3};"
        : "+f"(d[0]), "+f"(d[1]), "+f"(d[2]), "+f"(d[3])
        : "r"(a[0]), "r"(a[1]), "r"(a[2]), "r"(a[3]), "r"(b[0]), "r"(b[1]));
}

__global__ __launch_bounds__(256, 1) void node_gemm_mma(
    const float* __restrict__ z,
    const float* __restrict__ b1,
    int n_nodes)
{
    extern __shared__ __align__(16) unsigned char smem[];
    __nv_bfloat16* Ah = (__nv_bfloat16*)smem;            // [128][ASTRIDE]
    __nv_bfloat16* Al = Ah + 128 * ASTRIDE;
    __nv_bfloat16* Bh = Al + 128 * ASTRIDE;              // [128 n][ASTRIDE k]
    __nv_bfloat16* Bl = Bh + 128 * ASTRIDE;

    const int tid = threadIdx.x;
    const int wid = tid >> 5;
    const int lane = tid & 31;
    const int m0 = blockIdx.x * 128;

    // ---- load z tile [128 x 128] fp32 -> bf16 hi/lo (ONCE) ----
    #pragma unroll
    for (int i = 0; i < 16; i++) {
        int idx = tid + i * 256;        // 0..4095 float4 slots
        int r = idx >> 5;
        int c4 = idx & 31;
        float4 v = make_float4(0.f, 0.f, 0.f, 0.f);
        if (m0 + r < n_nodes)
            v = *(const float4*)(z + (size_t)(m0 + r) * H + c4 * 4);
        __nv_bfloat16 h0 = __float2bfloat16(v.x), h1 = __float2bfloat16(v.y);
        __nv_bfloat16 h2 = __float2bfloat16(v.z), h3 = __float2bfloat16(v.w);
        __nv_bfloat16 l0 = __float2bfloat16(v.x - __bfloat162float(h0));
        __nv_bfloat16 l1 = __float2bfloat16(v.y - __bfloat162float(h1));
        __nv_bfloat16 l2 = __float2bfloat16(v.z - __bfloat162float(h2));
        __nv_bfloat16 l3 = __float2bfloat16(v.w - __bfloat162float(h3));
        uint2 uh, ul;
        uh.x = ((uint32_t)__bfloat16_as_ushort(h1) << 16) | __bfloat16_as_ushort(h0);
        uh.y = ((uint32_t)__bfloat16_as_ushort(h3) << 16) | __bfloat16_as_ushort(h2);
        ul.x = ((uint32_t)__bfloat16_as_ushort(l1) << 16) | __bfloat16_as_ushort(l0);
        ul.y = ((uint32_t)__bfloat16_as_ushort(l3) << 16) | __bfloat16_as_ushort(l2);
        *(uint2*)((unsigned char*)Ah + r * (ASTRIDE * 2) + c4 * 8) = uh;
        *(uint2*)((unsigned char*)Al + r * (ASTRIDE * 2) + c4 * 8) = ul;
    }

    const int wm = wid & 3;
    const int wn = wid >> 2;
    const int gr = lane >> 2;
    const int cc = lane & 3;

    for (int h = 0; h < 2; h++) {
        __syncthreads();   // protect B smem from overwrite while others still read

        // ---- copy pre-transposed W images for this half ----
        {
            const uint4* shi = (const uint4*)(g_Wt_hi + (size_t)h * 128 * 128);
            const uint4* slo = (const uint4*)(g_Wt_lo + (size_t)h * 128 * 128);
            #pragma unroll
            for (int i = 0; i < 8; i++) {
                int idx = tid + i * 256;
                int r = idx >> 4;
                int q = idx & 15;
                *(uint4*)((unsigned char*)Bh + r * (ASTRIDE * 2) + q * 16) = shi[r * 16 + q];
                *(uint4*)((unsigned char*)Bl + r * (ASTRIDE * 2) + q * 16) = slo[r * 16 + q];
            }
        }
        __syncthreads();

        float acc[2][8][4];
        #pragma unroll
        for (int a = 0; a < 2; a++)
            #pragma unroll
            for (int b = 0; b < 8; b++)
                #pragma unroll
                for (int c = 0; c < 4; c++) acc[a][b][c] = 0.f;

        #pragma unroll
        for (int ks = 0; ks < 8; ks++) {
            const int kb = ks * 32 + cc * 4;
            uint32_t ah[2][4], al[2][4];
            #pragma unroll
            for (int mt = 0; mt < 2; mt++) {
                int row = wm * 32 + mt * 16 + gr;
                const unsigned char* pAh = (const unsigned char*)Ah + kb;
                const unsigned char* pAl = (const unsigned char*)Al + kb;
                ah[mt][0] = *(const uint32_t*)(pAh + (row)     * (ASTRIDE * 2));
                ah[mt][1] = *(const uint32_t*)(pAh + (row + 8) * (ASTRIDE * 2));
                ah[mt][2] = *(const uint32_t*)(pAh + (row)     * (ASTRIDE * 2) + 16);
                ah[mt][3] = *(const uint32_t*)(pAh + (row + 8) * (ASTRIDE * 2) + 16);
                al[mt][0] = *(const uint32_t*)(pAl + (row)     * (ASTRIDE * 2));
                al[mt][1] = *(const uint32_t*)(pAl + (row + 8) * (ASTRIDE * 2));
                al[mt][2] = *(const uint32_t*)(pAl + (row)     * (ASTRIDE * 2) + 16);
                al[mt][3] = *(const uint32_t*)(pAl + (row + 8) * (ASTRIDE * 2) + 16);
            }
            #pragma unroll
            for (int nt = 0; nt < 8; nt++) {
                int nrow = wn * 64 + nt * 8 + gr;
                const unsigned char* pB  = (const unsigned char*)Bh + nrow * (ASTRIDE * 2) + kb;
                const unsigned char* pBl = (const unsigned char*)Bl + nrow * (ASTRIDE * 2) + kb;
                uint32_t bh[2], bl[2];
                bh[0] = *(const uint32_t*)(pB);
                bh[1] = *(const uint32_t*)(pB + 16);
                bl[0] = *(const uint32_t*)(pBl);
                bl[1] = *(const uint32_t*)(pBl + 16);
                #pragma unroll
                for (int mt = 0; mt < 2; mt++) {
                    mma16816(acc[mt][nt], ah[mt], bh);
                    mma16816(acc[mt][nt], al[mt], bh);
                    mma16816(acc[mt][nt], ah[mt], bl);
                }
            }
        }

        // ---- epilogue: half2 writes, b1 fused on half 0 ----
        #pragma unroll
        for (int mt = 0; mt < 2; mt++) {
            #pragma unroll
            for (int nt = 0; nt < 8; nt++) {
                int nloc = wn * 64 + nt * 8 + cc * 2;
                int ncol = h * 128 + nloc;
                float bx = 0.f, by = 0.f;
                if (h == 0) {
                    float2 bb = __ldg((const float2*)(b1 + nloc));
                    bx = bb.x; by = bb.y;
                }
                int row0 = m0 + wm * 32 + mt * 16 + gr;
                if (row0 < n_nodes) {
                    __half2 v = __floats2half2_rn(acc[mt][nt][0] + bx, acc[mt][nt][1] + by);
                    *(__half2*)(g_ABh + (size_t)row0 * 256 + ncol) = v;
                }
                int row1 = row0 + 8;
                if (row1 < n_nodes) {
                    __half2 v = __floats2half2_rn(acc[mt][nt][2] + bx, acc[mt][nt][3] + by);
                    *(__half2*)(g_ABh + (size_t)row1 * 256 + ncol) = v;
                }
            }
        }
    }
}

#define SMEM_GEMM (4 * 128 * ASTRIDE * 2)   // 139264 bytes

// ---------------- Edge pass: 4 edges per warp (MLP=8) ----------------
__global__ __launch_bounds__(256) void edge_kernel(
    const void* __restrict__ eli_raw,
    const float* __restrict__ W2,
    const float* __restrict__ b2,
    float* __restrict__ out,
    int E, int n_nodes)
{
    __shared__ float w2s[128];
    const int tid = threadIdx.x;
    if (tid < 128) w2s[tid] = W2[tid];
    __syncthreads();

    const int lane = tid & 31;
    const int warp = tid >> 5;
    const int e0 = (blockIdx.x * 8 + warp) * 4;
    if (e0 >= E) return;

    // lanes 0..3 load r for edges e0..e0+3; lanes 4..7 load c
    int vidx = 0;
    if (lane < 8) {
        int e = e0 + (lane & 3);
        if (e >= E) e = E - 1;
        size_t off = (lane >= 4) ? ((size_t)E + e) : (size_t)e;
        if (g_idx_is64) vidx = (int)((const long long*)eli_raw)[off];
        else            vidx = ((const int*)eli_raw)[off];
        vidx = min(max(vidx, 0), n_nodes - 1);
    }

    uint2 av[4], bv[4];
    #pragma unroll
    for (int i = 0; i < 4; i++) {
        int r = __shfl_sync(0xffffffffu, vidx, i);
        int c = __shfl_sync(0xffffffffu, vidx, 4 + i);
        av[i] = *(const uint2*)(g_ABh + (size_t)r * 256 + lane * 4);
        bv[i] = *(const uint2*)(g_ABh + (size_t)c * 256 + 128 + lane * 4);
    }

    const float4 wv = *(const float4*)(w2s + lane * 4);
    const float bias = __ldg(b2);

    #pragma unroll
    for (int i = 0; i < 4; i++) {
        float2 a0 = __half22float2(*(__half2*)&av[i].x);
        float2 a1 = __half22float2(*(__half2*)&av[i].y);
        float2 c0 = __half22float2(*(__half2*)&bv[i].x);
        float2 c1 = __half22float2(*(__half2*)&bv[i].y);
        float s = fmaxf(a0.x + c0.x, 0.f) * wv.x
                + fmaxf(a0.y + c0.y, 0.f) * wv.y
                + fmaxf(a1.x + c1.x, 0.f) * wv.z
                + fmaxf(a1.y + c1.y, 0.f) * wv.w;
        #pragma unroll
        for (int o = 16; o; o >>= 1) s += __shfl_xor_sync(0xffffffffu, s, o);
        if (lane == 0 && e0 + i < E) out[e0 + i] = s + bias;
    }
}

extern "C" void kernel_launch(void* const* d_in, const int* in_sizes, int n_in,
                              void* d_out, int out_size)
{
    const float* z   = (const float*)d_in[0];
    const void*  eli = d_in[1];
    const float* W1  = (const float*)d_in[2];
    const float* b1  = (const float*)d_in[3];
    const float* W2  = (const float*)d_in[4];
    const float* b2  = (const float*)d_in[5];
    float*       out = (float*)d_out;

    const int n_nodes = in_sizes[0] / H;
    const int E = out_size;

    int n64 = E < 1024 ? E : 1024;
    detect_idx_kernel<<<1, 256>>>((const long long*)eli, n64);

    prep_w_kernel<<<32, 1024>>>(W1);

    cudaFuncSetAttribute(node_gemm_mma, cudaFuncAttributeMaxDynamicSharedMemorySize,
                         SMEM_GEMM);
    node_gemm_mma<<<(n_nodes + 127) / 128, 256, SMEM_GEMM>>>(z, b1, n_nodes);

    int blocks = (E + 31) / 32;
    edge_kernel<<<blocks, 256>>>(eli, W2, b2, out, E, n_nodes);
}